// round 6
// baseline (speedup 1.0000x reference)
#include <cuda_runtime.h>
#include <math.h>

#define LSEQ 256
#define EDIM 768
#define HDIM 384
#define NDOM 9
#define BMAX 2048

// device scratch (no allocation allowed)
__device__ float g_feature[(size_t)BMAX * EDIM];   // [B, 2H]: [shared | specific]
__device__ float g_h1[(size_t)BMAX * 64];
__device__ float g_hdom[(size_t)BMAX * HDIM];
__device__ int   g_counts[16];
__device__ int   g_idx[NDOM * BMAX];

// ---------------------------------------------------------------------------
// K1: fused masked-attention pooling, chunked online softmax (8 tokens/iter).
// ---------------------------------------------------------------------------
#define PT 8
__global__ void __launch_bounds__(192) pool_kernel(
    const float* __restrict__ bert, const int* __restrict__ masks,
    const float* __restrict__ att_w, const float* __restrict__ att_b,
    float* __restrict__ pooled)
{
    const int b = blockIdx.x, tid = threadIdx.x;
    const int lane = tid & 31, wid = tid >> 5;
    const float4* base = reinterpret_cast<const float4*>(bert + (size_t)b * LSEQ * EDIM);
    const float4 w = reinterpret_cast<const float4*>(att_w)[tid];
    const float bb = att_b[0];

    __shared__ float wr[2][PT][8];
    __shared__ int msk[LSEQ];
    for (int i = tid; i < LSEQ; i += 192) msk[i] = masks[b * LSEQ + i];

    float4 acc = make_float4(0.f, 0.f, 0.f, 0.f);
    float m = -3e38f, d = 0.f;

    float4 x[PT], xn[PT];
    #pragma unroll
    for (int j = 0; j < PT; ++j) x[j] = base[j * 192 + tid];
    __syncthreads();  // msk ready

    const int NC = LSEQ / PT;
    for (int c = 0; c < NC; ++c) {
        const int cb = c & 1;
        float p[PT];
        #pragma unroll
        for (int j = 0; j < PT; ++j)
            p[j] = x[j].x * w.x + x[j].y * w.y + x[j].z * w.z + x[j].w * w.w;

        if (c + 1 < NC) {
            #pragma unroll
            for (int j = 0; j < PT; ++j)
                xn[j] = base[((c + 1) * PT + j) * 192 + tid];
        }

        #pragma unroll
        for (int j = 0; j < PT; ++j) {
            #pragma unroll
            for (int o = 16; o; o >>= 1)
                p[j] += __shfl_xor_sync(0xffffffffu, p[j], o);
        }
        if (lane == 0) {
            #pragma unroll
            for (int j = 0; j < PT; ++j) wr[cb][j][wid] = p[j];
        }
        __syncthreads();

        float s[PT], Mc = -3e38f;
        #pragma unroll
        for (int j = 0; j < PT; ++j) {
            s[j] = wr[cb][j][0] + wr[cb][j][1] + wr[cb][j][2]
                 + wr[cb][j][3] + wr[cb][j][4] + wr[cb][j][5] + bb;
            if (msk[c * PT + j] == 0) s[j] = -1e9f;
            Mc = fmaxf(Mc, s[j]);
        }
        float pe[PT], dc = 0.f;
        #pragma unroll
        for (int j = 0; j < PT; ++j) { pe[j] = __expf(s[j] - Mc); dc += pe[j]; }
        float4 ca = make_float4(0.f, 0.f, 0.f, 0.f);
        #pragma unroll
        for (int j = 0; j < PT; ++j) {
            ca.x += pe[j] * x[j].x; ca.y += pe[j] * x[j].y;
            ca.z += pe[j] * x[j].z; ca.w += pe[j] * x[j].w;
        }
        const float nm = fmaxf(m, Mc);
        const float fo = __expf(m - nm), fn = __expf(Mc - nm);
        d = d * fo + dc * fn;
        acc.x = acc.x * fo + ca.x * fn;
        acc.y = acc.y * fo + ca.y * fn;
        acc.z = acc.z * fo + ca.z * fn;
        acc.w = acc.w * fo + ca.w * fn;
        m = nm;
        #pragma unroll
        for (int j = 0; j < PT; ++j) x[j] = xn[j];
    }
    const float inv = 1.f / d;
    float4 o = make_float4(acc.x * inv, acc.y * inv, acc.z * inv, acc.w * inv);
    reinterpret_cast<float4*>(pooled + (size_t)b * EDIM)[tid] = o;
}

// ---------------------------------------------------------------------------
// category routing lists
// ---------------------------------------------------------------------------
__global__ void zero_counts_kernel() { if (threadIdx.x < 16) g_counts[threadIdx.x] = 0; }

__global__ void scatter_kernel(const int* __restrict__ category, int B) {
    int i = blockIdx.x * blockDim.x + threadIdx.x;
    if (i < B) {
        int c = category[i];
        int p = atomicAdd(&g_counts[c], 1);
        g_idx[c * BMAX + p] = i;
    }
}

// ---------------------------------------------------------------------------
// 128x64-tile GEMM core pieces (8x4 micro-tile, 256 threads, double-buffered,
// one __syncthreads per 16-wide K-step). 32 FFMA per 3 LDS.128.
// ---------------------------------------------------------------------------
// Dense: C = relu(A[M,K] @ W[K,N] + bias). K%16==0, N%64==0.
__global__ void __launch_bounds__(256) gemm128_bias_relu(
    const float* __restrict__ A, int lda,
    const float* __restrict__ W, int ldw,
    const float* __restrict__ bias,
    float* __restrict__ C, int ldc,
    int M, int K)
{
    const int mt = blockIdx.y;
    const int colbase = blockIdx.x * 64;

    __shared__ float As[2][16][132];
    __shared__ float Bs[2][16][64];

    const int t = threadIdx.x;
    const int arow = t >> 1, acol = (t & 1) * 8;
    const int bk = t >> 4, bn = (t & 15) * 4;
    const int ty = t >> 4, tx = t & 15;

    const int ga = mt * 128 + arow;
    const bool al = (ga < M);
    const float* Ap = A + (size_t)(al ? ga : 0) * lda;

    float acc[8][4];
    #pragma unroll
    for (int i = 0; i < 8; ++i)
        #pragma unroll
        for (int j = 0; j < 4; ++j) acc[i][j] = 0.f;

    const int NS = K / 16;
    float4 a0 = make_float4(0.f,0.f,0.f,0.f), a1 = a0;
    if (al) {
        a0 = *reinterpret_cast<const float4*>(Ap + acol);
        a1 = *reinterpret_cast<const float4*>(Ap + acol + 4);
    }
    float4 bv = *reinterpret_cast<const float4*>(W + (size_t)bk * ldw + colbase + bn);
    As[0][acol + 0][arow] = a0.x; As[0][acol + 1][arow] = a0.y;
    As[0][acol + 2][arow] = a0.z; As[0][acol + 3][arow] = a0.w;
    As[0][acol + 4][arow] = a1.x; As[0][acol + 5][arow] = a1.y;
    As[0][acol + 6][arow] = a1.z; As[0][acol + 7][arow] = a1.w;
    *reinterpret_cast<float4*>(&Bs[0][bk][bn]) = bv;
    __syncthreads();

    for (int s = 0; s < NS; ++s) {
        const int cur = s & 1;
        float4 a0n = make_float4(0.f,0.f,0.f,0.f), a1n = a0n, bvn;
        if (s + 1 < NS) {
            const int k0 = (s + 1) * 16;
            if (al) {
                a0n = *reinterpret_cast<const float4*>(Ap + k0 + acol);
                a1n = *reinterpret_cast<const float4*>(Ap + k0 + acol + 4);
            }
            bvn = *reinterpret_cast<const float4*>(W + (size_t)(k0 + bk) * ldw + colbase + bn);
        }
        #pragma unroll
        for (int kk = 0; kk < 16; ++kk) {
            float4 x0 = *reinterpret_cast<const float4*>(&As[cur][kk][ty * 8]);
            float4 x1 = *reinterpret_cast<const float4*>(&As[cur][kk][ty * 8 + 4]);
            float4 b4 = *reinterpret_cast<const float4*>(&Bs[cur][kk][tx * 4]);
            float ar[8] = {x0.x, x0.y, x0.z, x0.w, x1.x, x1.y, x1.z, x1.w};
            float br[4] = {b4.x, b4.y, b4.z, b4.w};
            #pragma unroll
            for (int i = 0; i < 8; ++i)
                #pragma unroll
                for (int j = 0; j < 4; ++j) acc[i][j] += ar[i] * br[j];
        }
        if (s + 1 < NS) {
            const int nb = cur ^ 1;
            As[nb][acol + 0][arow] = a0n.x; As[nb][acol + 1][arow] = a0n.y;
            As[nb][acol + 2][arow] = a0n.z; As[nb][acol + 3][arow] = a0n.w;
            As[nb][acol + 4][arow] = a1n.x; As[nb][acol + 5][arow] = a1n.y;
            As[nb][acol + 6][arow] = a1n.z; As[nb][acol + 7][arow] = a1n.w;
            *reinterpret_cast<float4*>(&Bs[nb][bk][bn]) = bvn;
        }
        __syncthreads();
    }

    float4 bb4 = *reinterpret_cast<const float4*>(bias + colbase + tx * 4);
    float bb[4] = {bb4.x, bb4.y, bb4.z, bb4.w};
    #pragma unroll
    for (int i = 0; i < 8; ++i) {
        const int row = mt * 128 + ty * 8 + i;
        if (row < M) {
            float4 o;
            o.x = fmaxf(acc[i][0] + bb[0], 0.f);
            o.y = fmaxf(acc[i][1] + bb[1], 0.f);
            o.z = fmaxf(acc[i][2] + bb[2], 0.f);
            o.w = fmaxf(acc[i][3] + bb[3], 0.f);
            *reinterpret_cast<float4*>(C + (size_t)row * ldc + colbase + tx * 4) = o;
        }
    }
}

// Expert/shared fused: blockIdx.z 0..8 = gathered expert (out cols [H,2H)),
// 9 = dense shared MLP (out cols [0,H)). Same 128x64 / 8x4 core.
__global__ void __launch_bounds__(256) expert_gemm128(
    const float* __restrict__ pooled,
    const float* __restrict__ Wsh, const float* __restrict__ bsh,
    const float* __restrict__ Wsp, const float* __restrict__ bsp,
    int B)
{
    const int c = blockIdx.z;
    const bool dense = (c == NDOM);
    const int cnt = dense ? B : g_counts[c];
    const int mt = blockIdx.y;
    if (mt * 128 >= cnt) return;

    const float* W    = dense ? Wsh : (Wsp + (size_t)c * EDIM * HDIM);
    const float* bias = dense ? bsh : (bsp + c * HDIM);
    const int colbase = blockIdx.x * 64;
    const int outcol  = (dense ? 0 : HDIM) + colbase;

    __shared__ float As[2][16][132];
    __shared__ float Bs[2][16][64];

    const int t = threadIdx.x;
    const int arow = t >> 1, acol = (t & 1) * 8;
    const int bk = t >> 4, bn = (t & 15) * 4;
    const int ty = t >> 4, tx = t & 15;

    int gi = -1;
    {
        const int amrow = mt * 128 + arow;
        if (amrow < cnt) gi = dense ? amrow : g_idx[c * BMAX + amrow];
    }
    const bool al = (gi >= 0);
    const float* Ap = pooled + (size_t)(al ? gi : 0) * EDIM;

    float acc[8][4];
    #pragma unroll
    for (int i = 0; i < 8; ++i)
        #pragma unroll
        for (int j = 0; j < 4; ++j) acc[i][j] = 0.f;

    const int NS = EDIM / 16;
    float4 a0 = make_float4(0.f,0.f,0.f,0.f), a1 = a0;
    if (al) {
        a0 = *reinterpret_cast<const float4*>(Ap + acol);
        a1 = *reinterpret_cast<const float4*>(Ap + acol + 4);
    }
    float4 bv = *reinterpret_cast<const float4*>(W + (size_t)bk * HDIM + colbase + bn);
    As[0][acol + 0][arow] = a0.x; As[0][acol + 1][arow] = a0.y;
    As[0][acol + 2][arow] = a0.z; As[0][acol + 3][arow] = a0.w;
    As[0][acol + 4][arow] = a1.x; As[0][acol + 5][arow] = a1.y;
    As[0][acol + 6][arow] = a1.z; As[0][acol + 7][arow] = a1.w;
    *reinterpret_cast<float4*>(&Bs[0][bk][bn]) = bv;
    __syncthreads();

    for (int s = 0; s < NS; ++s) {
        const int cur = s & 1;
        float4 a0n = make_float4(0.f,0.f,0.f,0.f), a1n = a0n, bvn;
        if (s + 1 < NS) {
            const int k0 = (s + 1) * 16;
            if (al) {
                a0n = *reinterpret_cast<const float4*>(Ap + k0 + acol);
                a1n = *reinterpret_cast<const float4*>(Ap + k0 + acol + 4);
            }
            bvn = *reinterpret_cast<const float4*>(W + (size_t)(k0 + bk) * HDIM + colbase + bn);
        }
        #pragma unroll
        for (int kk = 0; kk < 16; ++kk) {
            float4 x0 = *reinterpret_cast<const float4*>(&As[cur][kk][ty * 8]);
            float4 x1 = *reinterpret_cast<const float4*>(&As[cur][kk][ty * 8 + 4]);
            float4 b4 = *reinterpret_cast<const float4*>(&Bs[cur][kk][tx * 4]);
            float ar[8] = {x0.x, x0.y, x0.z, x0.w, x1.x, x1.y, x1.z, x1.w};
            float br[4] = {b4.x, b4.y, b4.z, b4.w};
            #pragma unroll
            for (int i = 0; i < 8; ++i)
                #pragma unroll
                for (int j = 0; j < 4; ++j) acc[i][j] += ar[i] * br[j];
        }
        if (s + 1 < NS) {
            const int nb = cur ^ 1;
            As[nb][acol + 0][arow] = a0n.x; As[nb][acol + 1][arow] = a0n.y;
            As[nb][acol + 2][arow] = a0n.z; As[nb][acol + 3][arow] = a0n.w;
            As[nb][acol + 4][arow] = a1n.x; As[nb][acol + 5][arow] = a1n.y;
            As[nb][acol + 6][arow] = a1n.z; As[nb][acol + 7][arow] = a1n.w;
            *reinterpret_cast<float4*>(&Bs[nb][bk][bn]) = bvn;
        }
        __syncthreads();
    }

    float4 bb4 = *reinterpret_cast<const float4*>(bias + colbase + tx * 4);
    float bb[4] = {bb4.x, bb4.y, bb4.z, bb4.w};
    #pragma unroll
    for (int i = 0; i < 8; ++i) {
        const int grow = mt * 128 + ty * 8 + i;
        if (grow < cnt) {
            const int ridx = dense ? grow : g_idx[c * BMAX + grow];
            float4 o;
            o.x = fmaxf(acc[i][0] + bb[0], 0.f);
            o.y = fmaxf(acc[i][1] + bb[1], 0.f);
            o.z = fmaxf(acc[i][2] + bb[2], 0.f);
            o.w = fmaxf(acc[i][3] + bb[3], 0.f);
            *reinterpret_cast<float4*>(&g_feature[(size_t)ridx * EDIM + outcol + tx * 4]) = o;
        }
    }
}

// ---------------------------------------------------------------------------
// Small-BM double-buffered GEMM (for dec1: N=64, BM=16 -> 128 CTAs).
// ---------------------------------------------------------------------------
template<int MM>
__global__ void __launch_bounds__(256) gemm_bias_relu(
    const float* __restrict__ A, int lda,
    const float* __restrict__ W, int ldw,
    const float* __restrict__ bias,
    float* __restrict__ C, int ldc,
    int M, int K)
{
    constexpr int BM = 16 * MM;
    constexpr int APAD = BM + 4;
    const int mt = blockIdx.y;
    const int colbase = blockIdx.x * 64;

    __shared__ float As[2][16][APAD];
    __shared__ float Bs[2][16][64];

    const int t = threadIdx.x;
    const int arow = t >> 2, akk = (t & 3) * 4;
    const int bk = t >> 4, bn = (t & 15) * 4;
    const int ty = t >> 4, tx = t & 15;

    const int ga = mt * BM + arow;
    const bool aload = (arow < BM) && (ga < M);
    const float* Ap = A + (size_t)(aload ? ga : 0) * lda;

    float acc[MM][4];
    #pragma unroll
    for (int i = 0; i < MM; ++i)
        #pragma unroll
        for (int j = 0; j < 4; ++j) acc[i][j] = 0.f;

    const int NS = K / 16;
    float4 av = make_float4(0.f, 0.f, 0.f, 0.f);
    if (aload) av = *reinterpret_cast<const float4*>(Ap + akk);
    float4 bv = *reinterpret_cast<const float4*>(W + (size_t)bk * ldw + colbase + bn);
    if (arow < BM) {
        As[0][akk + 0][arow] = av.x; As[0][akk + 1][arow] = av.y;
        As[0][akk + 2][arow] = av.z; As[0][akk + 3][arow] = av.w;
    }
    *reinterpret_cast<float4*>(&Bs[0][bk][bn]) = bv;
    __syncthreads();

    for (int s = 0; s < NS; ++s) {
        const int cur = s & 1;
        float4 av2 = make_float4(0.f, 0.f, 0.f, 0.f), bv2;
        if (s + 1 < NS) {
            const int k0 = (s + 1) * 16;
            if (aload) av2 = *reinterpret_cast<const float4*>(Ap + k0 + akk);
            bv2 = *reinterpret_cast<const float4*>(W + (size_t)(k0 + bk) * ldw + colbase + bn);
        }
        #pragma unroll
        for (int kk = 0; kk < 16; ++kk) {
            float a[MM];
            #pragma unroll
            for (int i = 0; i < MM; ++i) a[i] = As[cur][kk][ty * MM + i];
            float4 b4 = *reinterpret_cast<const float4*>(&Bs[cur][kk][tx * 4]);
            float br[4] = {b4.x, b4.y, b4.z, b4.w};
            #pragma unroll
            for (int i = 0; i < MM; ++i)
                #pragma unroll
                for (int j = 0; j < 4; ++j) acc[i][j] += a[i] * br[j];
        }
        if (s + 1 < NS) {
            const int nb = cur ^ 1;
            if (arow < BM) {
                As[nb][akk + 0][arow] = av2.x; As[nb][akk + 1][arow] = av2.y;
                As[nb][akk + 2][arow] = av2.z; As[nb][akk + 3][arow] = av2.w;
            }
            *reinterpret_cast<float4*>(&Bs[nb][bk][bn]) = bv2;
        }
        __syncthreads();
    }

    float4 bb4 = *reinterpret_cast<const float4*>(bias + colbase + tx * 4);
    float bb[4] = {bb4.x, bb4.y, bb4.z, bb4.w};
    #pragma unroll
    for (int i = 0; i < MM; ++i) {
        const int row = mt * BM + ty * MM + i;
        if (row < M) {
            float4 o;
            o.x = fmaxf(acc[i][0] + bb[0], 0.f);
            o.y = fmaxf(acc[i][1] + bb[1], 0.f);
            o.z = fmaxf(acc[i][2] + bb[2], 0.f);
            o.w = fmaxf(acc[i][3] + bb[3], 0.f);
            *reinterpret_cast<float4*>(C + (size_t)row * ldc + colbase + tx * 4) = o;
        }
    }
}

// ---------------------------------------------------------------------------
// classifier: warp per sample, out = sigmoid(feature . Wc + bc)
// ---------------------------------------------------------------------------
__global__ void __launch_bounds__(256) cls_kernel(
    const float* __restrict__ Wc, const float* __restrict__ bc,
    float* __restrict__ out, int B)
{
    const int warp = (blockIdx.x * 256 + threadIdx.x) >> 5;
    const int lane = threadIdx.x & 31;
    if (warp >= B) return;
    const float4* f = reinterpret_cast<const float4*>(g_feature + (size_t)warp * EDIM);
    const float4* wc = reinterpret_cast<const float4*>(Wc);
    float acc = 0.f;
    #pragma unroll
    for (int i = 0; i < 6; ++i) {
        float4 a = f[lane + 32 * i], ww = wc[lane + 32 * i];
        acc += a.x * ww.x + a.y * ww.y + a.z * ww.z + a.w * ww.w;
    }
    #pragma unroll
    for (int o = 16; o; o >>= 1) acc += __shfl_xor_sync(0xffffffffu, acc, o);
    if (lane == 0) out[warp] = 1.f / (1.f + __expf(-(acc + bc[0])));
}

// ---------------------------------------------------------------------------
// domain head stage 2: warp per sample, dp = hdom @ Wdo2 + bdo2 (N=9)
// ---------------------------------------------------------------------------
__global__ void __launch_bounds__(256) domain2_kernel(
    const float* __restrict__ Wdo2, const float* __restrict__ bdo2,
    float* __restrict__ dp, int B)
{
    const int warp = (blockIdx.x * 256 + threadIdx.x) >> 5;
    const int lane = threadIdx.x & 31;
    if (warp >= B) return;
    const float* h = g_hdom + (size_t)warp * HDIM;
    float a[NDOM];
    #pragma unroll
    for (int j = 0; j < NDOM; ++j) a[j] = 0.f;
    #pragma unroll
    for (int i = 0; i < 3; ++i) {
        const int k = (lane + 32 * i) * 4;
        float4 hv = *reinterpret_cast<const float4*>(h + k);
        float hh[4] = {hv.x, hv.y, hv.z, hv.w};
        #pragma unroll
        for (int q = 0; q < 4; ++q) {
            const float* wrow = Wdo2 + (k + q) * NDOM;
            #pragma unroll
            for (int j = 0; j < NDOM; ++j) a[j] += hh[q] * wrow[j];
        }
    }
    #pragma unroll
    for (int j = 0; j < NDOM; ++j) {
        #pragma unroll
        for (int o = 16; o; o >>= 1) a[j] += __shfl_xor_sync(0xffffffffu, a[j], o);
    }
    if (lane == 0) {
        #pragma unroll
        for (int j = 0; j < NDOM; ++j)
            dp[(size_t)warp * NDOM + j] = a[j] + bdo2[j];
    }
}

// ---------------------------------------------------------------------------
extern "C" void kernel_launch(void* const* d_in, const int* in_sizes, int n_in,
                              void* d_out, int out_size)
{
    const float* bert     = (const float*)d_in[0];
    const int*   masks    = (const int*)d_in[1];
    const int*   category = (const int*)d_in[2];
    const float* att_w = (const float*)d_in[4];
    const float* att_b = (const float*)d_in[5];
    const float* Wsh = (const float*)d_in[6];  const float* bsh = (const float*)d_in[7];
    const float* Wsp = (const float*)d_in[8];  const float* bsp = (const float*)d_in[9];
    const float* Wd1 = (const float*)d_in[10]; const float* bd1 = (const float*)d_in[11];
    const float* Wd2 = (const float*)d_in[12]; const float* bd2 = (const float*)d_in[13];
    const float* Wc  = (const float*)d_in[14]; const float* bc  = (const float*)d_in[15];
    const float* Wdo1 = (const float*)d_in[16]; const float* bdo1 = (const float*)d_in[17];
    const float* Wdo2 = (const float*)d_in[18]; const float* bdo2 = (const float*)d_in[19];

    const int B = in_sizes[2];

    float* out    = (float*)d_out;
    float* rec    = out + B;
    float* pooled = rec + (size_t)B * EDIM;
    float* dp     = pooled + (size_t)B * EDIM;

    // TRUE device addresses of __device__ scratch (host shadow address is
    // ATS-reachable on GB300 and silently corrupts — R2/R3 lesson).
    float *p_feature = nullptr, *p_h1 = nullptr, *p_hdom = nullptr;
    cudaGetSymbolAddress((void**)&p_feature, g_feature);
    cudaGetSymbolAddress((void**)&p_h1, g_h1);
    cudaGetSymbolAddress((void**)&p_hdom, g_hdom);

    // routing lists (off the data critical path)
    zero_counts_kernel<<<1, 16>>>();
    scatter_kernel<<<(B + 255) / 256, 256>>>(category, B);

    pool_kernel<<<B, 192>>>(bert, masks, att_w, att_b, pooled);

    // shared MLP (slab 9) + 9 specific experts in one launch, 128x64 tiles
    expert_gemm128<<<dim3(HDIM / 64, (B + 127) / 128, NDOM + 1), 256>>>(
        pooled, Wsh, bsh, Wsp, bsp, B);

    // decoder stage 1: [B,768]@[768,64] -> g_h1  (BM=16 -> 128 CTAs)
    gemm_bias_relu<1><<<dim3(1, (B + 15) / 16), 256>>>(
        p_feature, EDIM, Wd1, 64, bd1, p_h1, 64, B, EDIM);

    // domain stage 1: [B,384]@[384,384] -> g_hdom (shared = cols 0:384)
    gemm128_bias_relu<<<dim3(HDIM / 64, (B + 127) / 128), 256>>>(
        p_feature, EDIM, Wdo1, HDIM, bdo1, p_hdom, HDIM, B, HDIM);

    // classifier head
    cls_kernel<<<(B * 32 + 255) / 256, 256>>>(Wc, bc, out, B);

    // domain stage 2
    domain2_kernel<<<(B * 32 + 255) / 256, 256>>>(Wdo2, bdo2, dp, B);

    // decoder stage 2: [B,64]@[64,768] -> rec
    gemm128_bias_relu<<<dim3(EDIM / 64, (B + 127) / 128), 256>>>(
        p_h1, 64, Wd2, EDIM, bd2, rec, EDIM, B, 64);
}